// round 8
// baseline (speedup 1.0000x reference)
#include <cuda_runtime.h>
#include <cuda_bf16.h>
#include <float.h>
#include <stdint.h>

#define Bb 2
#define Ss 2048
#define Dd 768
#define Hh 12
#define DH 64
#define Mm (Bb*Ss)

// ---------------- scratch ----------------
__device__ float g_Q[(size_t)Bb*Hh*Ss*DH];
__device__ float g_K[(size_t)Bb*Hh*Ss*DH];
__device__ float g_V[(size_t)Bb*Hh*Ss*DH];
__device__ __nv_bfloat16 g_Oh[(size_t)Mm*Dd];
__device__ __nv_bfloat16 g_Ol[(size_t)Mm*Dd];
__device__ __nv_bfloat16 g_Xh[(size_t)Mm*Dd];
__device__ __nv_bfloat16 g_Xl[(size_t)Mm*Dd];
__device__ __nv_bfloat16 g_Wh[4][(size_t)Dd*Dd];
__device__ __nv_bfloat16 g_Wl[4][(size_t)Dd*Dd];

// ---------------- helpers ----------------
__device__ __forceinline__ uint32_t smem_u32(const void* p) {
    uint32_t a;
    asm("{ .reg .u64 t; cvta.to.shared.u64 t, %1; cvt.u32.u64 %0, t; }" : "=r"(a) : "l"(p));
    return a;
}
__device__ __forceinline__ void cp16(uint32_t dst, const void* src) {
    asm volatile("cp.async.cg.shared.global [%0], [%1], 16;"
        :: "r"(dst), "l"(__cvta_generic_to_global(src)));
}
__device__ __forceinline__ void cp_commit() { asm volatile("cp.async.commit_group;"); }
__device__ __forceinline__ void cp_wait0()  { asm volatile("cp.async.wait_group 0;"); }

__device__ __forceinline__ float to_tf32(float x) {
    uint32_t u;
    asm("cvt.rna.tf32.f32 %0, %1;" : "=r"(u) : "f"(x));
    return __uint_as_float(u);
}
__device__ __forceinline__ uint32_t f2u(float x) { return __float_as_uint(x); }

// tf32 k8 MMA (attention)
__device__ __forceinline__ void mma8(float* d, const uint32_t* a, const uint32_t* b) {
    asm volatile("mma.sync.aligned.m16n8k8.row.col.f32.tf32.tf32.f32 "
        "{%0,%1,%2,%3}, {%4,%5,%6,%7}, {%8,%9}, {%0,%1,%2,%3};"
        : "+f"(d[0]), "+f"(d[1]), "+f"(d[2]), "+f"(d[3])
        : "r"(a[0]), "r"(a[1]), "r"(a[2]), "r"(a[3]), "r"(b[0]), "r"(b[1]));
}
// bf16 k16 MMA (dense GEMMs)
__device__ __forceinline__ void mma16(float* d, const uint32_t* a, const uint32_t* b) {
    asm volatile("mma.sync.aligned.m16n8k16.row.col.f32.bf16.bf16.f32 "
        "{%0,%1,%2,%3}, {%4,%5,%6,%7}, {%8,%9}, {%0,%1,%2,%3};"
        : "+f"(d[0]), "+f"(d[1]), "+f"(d[2]), "+f"(d[3])
        : "r"(a[0]), "r"(a[1]), "r"(a[2]), "r"(a[3]), "r"(b[0]), "r"(b[1]));
}
__device__ __forceinline__ void ldm4(uint32_t* r, uint32_t addr) {
    asm volatile("ldmatrix.sync.aligned.m8n8.x4.shared.b16 {%0,%1,%2,%3}, [%4];"
        : "=r"(r[0]), "=r"(r[1]), "=r"(r[2]), "=r"(r[3]) : "r"(addr));
}
__device__ __forceinline__ void decb(float x, __nv_bfloat16& h, __nv_bfloat16& l) {
    h = __float2bfloat16_rn(x);
    l = __float2bfloat16_rn(x - __bfloat162float(h));
}

// ---------------- pre-pass: fp32 -> bf16 hi/lo ----------------
__global__ void conv_all(const float* __restrict__ x,
                         const float* __restrict__ wq, const float* __restrict__ wk,
                         const float* __restrict__ wv, const float* __restrict__ wo) {
    int i = blockIdx.x * blockDim.x + threadIdx.x;
    int stride = gridDim.x * blockDim.x;
    for (int t = i; t < Mm * Dd; t += stride) decb(x[t], g_Xh[t], g_Xl[t]);
    const float* ws[4] = {wq, wk, wv, wo};
    for (int w = 0; w < 4; w++)
        for (int t = i; t < Dd * Dd; t += stride) decb(ws[w][t], g_Wh[w][t], g_Wl[w][t]);
}

// ---------------- bf16x3 GEMM core, BK=32, 2-stage, term-major MMA order ----------------
// CTA 128x128, 256 threads (8 warps: wm 0..3, wn 0..1), warp tile 32x64.
// Stage: Ah[128][40] | Al | Bh | Bl bf16 = 40960 B. Row stride 80 B (conflict-free ldmatrix).
#define GSTG_B 40960
#define GCH32 24            // 768 / 32

__device__ __forceinline__ void gemm_core_bf3(const __nv_bfloat16* __restrict__ Ah,
                                              const __nv_bfloat16* __restrict__ Al,
                                              const __nv_bfloat16* __restrict__ Bh,
                                              const __nv_bfloat16* __restrict__ Bl,
                                              char* smc, float acc[2][8][4]) {
    const int tid = threadIdx.x;
    const int lane = tid & 31;
    const int wid = tid >> 5;
    const int wm = wid >> 1, wn = wid & 1;

    uint32_t sb = smem_u32(smc);

    #pragma unroll
    for (int mt = 0; mt < 2; mt++)
        #pragma unroll
        for (int nt = 0; nt < 8; nt++)
            #pragma unroll
            for (int q = 0; q < 4; q++) acc[mt][nt][q] = 0.f;

    const int r0l = tid >> 2, s0l = tid & 3;
    const int r1l = (256 + tid) >> 2;
    const uint32_t so0 = (uint32_t)(r0l * 80 + s0l * 16);
    const uint32_t so1 = (uint32_t)(r1l * 80 + s0l * 16);
    const size_t go0 = (size_t)r0l * Dd + s0l * 8;
    const size_t go1 = (size_t)r1l * Dd + s0l * 8;

    const int arow = lane & 15, acolb = ((lane >> 4) << 4);
    const uint32_t aoff0 = (uint32_t)((wm * 32 + arow) * 80) + acolb;
    const uint32_t aoff1 = aoff0 + 16 * 80;
    const int brow = ((lane >> 4) << 3) + (lane & 7);
    const int bcolb = (((lane >> 3) & 1) << 4);
    uint32_t boff[4];
    #pragma unroll
    for (int p = 0; p < 4; p++)
        boff[p] = (uint32_t)((wn * 64 + p * 16 + brow) * 80) + bcolb;

    // prologue: chunk 0 -> stage 0
    {
        cp16(sb + so0,          Ah + go0);
        cp16(sb + so1,          Ah + go1);
        cp16(sb + 10240 + so0,  Al + go0);
        cp16(sb + 10240 + so1,  Al + go1);
        cp16(sb + 20480 + so0,  Bh + go0);
        cp16(sb + 20480 + so1,  Bh + go1);
        cp16(sb + 30720 + so0,  Bl + go0);
        cp16(sb + 30720 + so1,  Bl + go1);
        cp_commit();
    }

    for (int c = 0; c < GCH32; c++) {
        cp_wait0();
        __syncthreads();
        if (c + 1 < GCH32) {
            uint32_t st = sb + ((c + 1) & 1) * GSTG_B;
            const size_t kq = (size_t)(c + 1) * 32;
            cp16(st + so0,          Ah + go0 + kq);
            cp16(st + so1,          Ah + go1 + kq);
            cp16(st + 10240 + so0,  Al + go0 + kq);
            cp16(st + 10240 + so1,  Al + go1 + kq);
            cp16(st + 20480 + so0,  Bh + go0 + kq);
            cp16(st + 20480 + so1,  Bh + go1 + kq);
            cp16(st + 30720 + so0,  Bl + go0 + kq);
            cp16(st + 30720 + so1,  Bl + go1 + kq);
            cp_commit();
        }

        const uint32_t st  = sb + (c & 1) * GSTG_B;
        #pragma unroll
        for (int kh = 0; kh < 2; kh++) {
            const uint32_t ko = kh * 32;
            const uint32_t stA  = st + ko,          stAl = st + 10240 + ko;
            const uint32_t stB  = st + 20480 + ko,  stBl = st + 30720 + ko;

            uint32_t ah[2][4], al[2][4];
            ldm4(ah[0], stA  + aoff0);
            ldm4(ah[1], stA  + aoff1);
            ldm4(al[0], stAl + aoff0);
            ldm4(al[1], stAl + aoff1);

            uint32_t bh[2][4], bl[2][4];
            ldm4(bh[0], stB  + boff[0]);
            ldm4(bl[0], stBl + boff[0]);
            #pragma unroll
            for (int p = 0; p < 4; p++) {
                const int cur = p & 1, nxt = cur ^ 1;
                if (p < 3) {
                    ldm4(bh[nxt], stB  + boff[p + 1]);
                    ldm4(bl[nxt], stBl + boff[p + 1]);
                }
                // term-major: 4 independent MMAs per term -> dependency distance 4
                #pragma unroll
                for (int j = 0; j < 2; j++)
                    #pragma unroll
                    for (int mt = 0; mt < 2; mt++)
                        mma16(acc[mt][p * 2 + j], al[mt], &bh[cur][2 * j]);
                #pragma unroll
                for (int j = 0; j < 2; j++)
                    #pragma unroll
                    for (int mt = 0; mt < 2; mt++)
                        mma16(acc[mt][p * 2 + j], ah[mt], &bl[cur][2 * j]);
                #pragma unroll
                for (int j = 0; j < 2; j++)
                    #pragma unroll
                    for (int mt = 0; mt < 2; mt++)
                        mma16(acc[mt][p * 2 + j], ah[mt], &bh[cur][2 * j]);
            }
        }
    }
}

// QKV projection: scatter fp32 (tf32-rounded, Q pre-scaled) into [B,H,S,DH]
__global__ __launch_bounds__(256, 2) void gemm_qkv_tc() {
    extern __shared__ char smc[];
    const int z = blockIdx.z;
    float* Obuf = (z == 0) ? g_Q : (z == 1 ? g_K : g_V);
    const float scale = (z == 0) ? 0.125f : 1.0f;
    const int mBase = blockIdx.x * 128, nBase = blockIdx.y * 128;

    float acc[2][8][4];
    gemm_core_bf3(g_Xh + (size_t)mBase * Dd, g_Xl + (size_t)mBase * Dd,
                  g_Wh[z] + (size_t)nBase * Dd, g_Wl[z] + (size_t)nBase * Dd,
                  smc, acc);

    const int lane = threadIdx.x & 31, wid = threadIdx.x >> 5;
    const int wm = wid >> 1, wn = wid & 1;
    const int h = (nBase + wn * 64) >> 6;
    #pragma unroll
    for (int mt = 0; mt < 2; mt++) {
        int r0 = mBase + wm * 32 + mt * 16 + (lane >> 2);
        #pragma unroll
        for (int half = 0; half < 2; half++) {
            int row = r0 + half * 8;
            int bb = row >> 11, ssi = row & 2047;
            float* dst = Obuf + (((size_t)bb * Hh + h) * Ss + ssi) * DH;
            #pragma unroll
            for (int nt = 0; nt < 8; nt++) {
                int d = nt * 8 + 2 * (lane & 3);
                *(float2*)(dst + d) = make_float2(
                    to_tf32(acc[mt][nt][half * 2 + 0] * scale),
                    to_tf32(acc[mt][nt][half * 2 + 1] * scale));
            }
        }
    }
}

// output projection: fp32 store to d_out
__global__ __launch_bounds__(256, 2) void gemm_out_tc(float* __restrict__ C) {
    extern __shared__ char smc[];
    const int mBase = blockIdx.x * 128, nBase = blockIdx.y * 128;

    float acc[2][8][4];
    gemm_core_bf3(g_Oh + (size_t)mBase * Dd, g_Ol + (size_t)mBase * Dd,
                  g_Wh[3] + (size_t)nBase * Dd, g_Wl[3] + (size_t)nBase * Dd,
                  smc, acc);

    const int lane = threadIdx.x & 31, wid = threadIdx.x >> 5;
    const int wm = wid >> 1, wn = wid & 1;
    #pragma unroll
    for (int mt = 0; mt < 2; mt++) {
        int r0 = mBase + wm * 32 + mt * 16 + (lane >> 2);
        #pragma unroll
        for (int half = 0; half < 2; half++) {
            int row = r0 + half * 8;
            float* dst = C + (size_t)row * Dd + nBase + wn * 64;
            #pragma unroll
            for (int nt = 0; nt < 8; nt++) {
                int d = nt * 8 + 2 * (lane & 3);
                *(float2*)(dst + d) = make_float2(acc[mt][nt][half * 2 + 0],
                                                  acc[mt][nt][half * 2 + 1]);
            }
        }
    }
}

// ---------------- flash attention (unchanged) ----------------
#define QS_OFF 0
#define KS_OFF 8704
#define VS_OFF 13056
#define PS_OFF 17664

__global__ __launch_bounds__(128) void attn_mma() {
    extern __shared__ float sm[];
    float* Qs = sm + QS_OFF;
    float* Ks = sm + KS_OFF;
    float* Vs = sm + VS_OFF;
    float* Ps = sm + PS_OFF;

    const int tid = threadIdx.x;
    const int lane = tid & 31, wid = tid >> 5;
    const int qt = gridDim.x - 1 - blockIdx.x;
    const int h = blockIdx.y, b = blockIdx.z;

    const float* Qg = g_Q + (((size_t)b * Hh + h) * Ss + (size_t)qt * 128) * DH;
    const float* Kg = g_K + (((size_t)b * Hh + h) * Ss) * DH;
    const float* Vg = g_V + (((size_t)b * Hh + h) * Ss) * DH;

    uint32_t sQ = smem_u32(Qs), sK = smem_u32(Ks), sV = smem_u32(Vs);

    #pragma unroll
    for (int t = 0; t < 16; t++) {
        int idx = tid + t * 128;
        int r = idx >> 4, c = (idx & 15) * 4;
        cp16(sQ + (r * 68 + c) * 4, Qg + r * DH + c);
    }
    cp_commit();

    float o[2][8][4];
    float mrow[2][2], lrow[2][2];
    #pragma unroll
    for (int mt = 0; mt < 2; mt++) {
        mrow[mt][0] = mrow[mt][1] = -1e30f;
        lrow[mt][0] = lrow[mt][1] = 0.f;
        #pragma unroll
        for (int nt = 0; nt < 8; nt++)
            #pragma unroll
            for (int q = 0; q < 4; q++) o[mt][nt][q] = 0.f;
    }

    const int cL = lane & 3, rL = lane >> 2;
    const int ktMax = 2 * qt + 1;

    for (int kt = 0; kt <= ktMax; kt++) {
        __syncthreads();
        const float* Kp = Kg + (size_t)kt * 64 * DH;
        const float* Vp = Vg + (size_t)kt * 64 * DH;
        #pragma unroll
        for (int t = 0; t < 8; t++) {
            int idx = tid + t * 128;
            int r = idx >> 4, c = (idx & 15) * 4;
            cp16(sK + (r * 68 + c) * 4, Kp + r * DH + c);
            cp16(sV + (r * 72 + c) * 4, Vp + r * DH + c);
        }
        cp_commit();
        cp_wait0();
        __syncthreads();

        float s[2][8][4];
        #pragma unroll
        for (int mt = 0; mt < 2; mt++)
            #pragma unroll
            for (int nt = 0; nt < 8; nt++)
                #pragma unroll
                for (int q = 0; q < 4; q++) s[mt][nt][q] = 0.f;

        #pragma unroll
        for (int ks = 0; ks < 8; ks++) {
            const int kb = ks * 8 + cL;
            uint32_t bfr[8][2];
            #pragma unroll
            for (int nt = 0; nt < 8; nt++) {
                const float* kp = Ks + (nt * 8 + rL) * 68;
                bfr[nt][0] = f2u(kp[kb]);
                bfr[nt][1] = f2u(kp[kb + 4]);
            }
            #pragma unroll
            for (int mt = 0; mt < 2; mt++) {
                const float* qp = Qs + (wid * 32 + mt * 16 + rL) * 68;
                uint32_t a[4];
                a[0] = f2u(qp[kb]);
                a[1] = f2u(qp[8 * 68 + kb]);
                a[2] = f2u(qp[kb + 4]);
                a[3] = f2u(qp[8 * 68 + kb + 4]);
                #pragma unroll
                for (int nt = 0; nt < 8; nt++) mma8(s[mt][nt], a, bfr[nt]);
            }
        }

        if (kt >= 2 * qt) {
            #pragma unroll
            for (int mt = 0; mt < 2; mt++) {
                int rg0 = qt * 128 + wid * 32 + mt * 16 + rL;
                #pragma unroll
                for (int nt = 0; nt < 8; nt++) {
                    int cg = kt * 64 + nt * 8 + 2 * cL;
                    if (cg     > rg0)     s[mt][nt][0] = -1e30f;
                    if (cg + 1 > rg0)     s[mt][nt][1] = -1e30f;
                    if (cg     > rg0 + 8) s[mt][nt][2] = -1e30f;
                    if (cg + 1 > rg0 + 8) s[mt][nt][3] = -1e30f;
                }
            }
        }

        #pragma unroll
        for (int mt = 0; mt < 2; mt++) {
            float v0 = -1e30f, v1 = -1e30f;
            #pragma unroll
            for (int nt = 0; nt < 8; nt++) {
                v0 = fmaxf(v0, fmaxf(s[mt][nt][0], s[mt][nt][1]));
                v1 = fmaxf(v1, fmaxf(s[mt][nt][2], s[mt][nt][3]));
            }
            v0 = fmaxf(v0, __shfl_xor_sync(0xffffffffu, v0, 1));
            v0 = fmaxf(v0, __shfl_xor_sync(0xffffffffu, v0, 2));
            v1 = fmaxf(v1, __shfl_xor_sync(0xffffffffu, v1, 1));
            v1 = fmaxf(v1, __shfl_xor_sync(0xffffffffu, v1, 2));

            float mn0 = fmaxf(mrow[mt][0], v0);
            float mn1 = fmaxf(mrow[mt][1], v1);
            float cr0 = __expf(mrow[mt][0] - mn0);
            float cr1 = __expf(mrow[mt][1] - mn1);
            mrow[mt][0] = mn0; mrow[mt][1] = mn1;

            float rs0 = 0.f, rs1 = 0.f;
            float* prow0 = Ps + (wid * 32 + mt * 16 + rL) * 72;
            float* prow1 = prow0 + 8 * 72;
            #pragma unroll
            for (int nt = 0; nt < 8; nt++) {
                float p0 = __expf(s[mt][nt][0] - mn0);
                float p1 = __expf(s[mt][nt][1] - mn0);
                float p2 = __expf(s[mt][nt][2] - mn1);
                float p3 = __expf(s[mt][nt][3] - mn1);
                rs0 += p0 + p1; rs1 += p2 + p3;
                int cc = nt * 8 + 2 * cL;
                *(float2*)(prow0 + cc) = make_float2(to_tf32(p0), to_tf32(p1));
                *(float2*)(prow1 + cc) = make_float2(to_tf32(p2), to_tf32(p3));
            }
            rs0 += __shfl_xor_sync(0xffffffffu, rs0, 1);
            rs0 += __shfl_xor_sync(0xffffffffu, rs0, 2);
            rs1 += __shfl_xor_sync(0xffffffffu, rs1, 1);
            rs1 += __shfl_xor_sync(0xffffffffu, rs1, 2);
            lrow[mt][0] = lrow[mt][0] * cr0 + rs0;
            lrow[mt][1] = lrow[mt][1] * cr1 + rs1;
            #pragma unroll
            for (int nt = 0; nt < 8; nt++) {
                o[mt][nt][0] *= cr0; o[mt][nt][1] *= cr0;
                o[mt][nt][2] *= cr1; o[mt][nt][3] *= cr1;
            }
        }
        __syncwarp();

        #pragma unroll
        for (int ks = 0; ks < 8; ks++) {
            const int kb = ks * 8;
            uint32_t bfr[8][2];
            #pragma unroll
            for (int nt = 0; nt < 8; nt++) {
                bfr[nt][0] = f2u(Vs[(kb + cL) * 72 + nt * 8 + rL]);
                bfr[nt][1] = f2u(Vs[(kb + 4 + cL) * 72 + nt * 8 + rL]);
            }
            #pragma unroll
            for (int mt = 0; mt < 2; mt++) {
                const float* pp = Ps + (wid * 32 + mt * 16 + rL) * 72;
                uint32_t a[4];
                a[0] = f2u(pp[kb + cL]);
                a[1] = f2u(pp[8 * 72 + kb + cL]);
                a[2] = f2u(pp[kb + 4 + cL]);
                a[3] = f2u(pp[8 * 72 + kb + 4 + cL]);
                #pragma unroll
                for (int nt = 0; nt < 8; nt++) mma8(o[mt][nt], a, bfr[nt]);
            }
        }
    }

    #pragma unroll
    for (int mt = 0; mt < 2; mt++) {
        float inv0 = 1.f / lrow[mt][0];
        float inv1 = 1.f / lrow[mt][1];
        int r0 = qt * 128 + wid * 32 + mt * 16 + rL;
        size_t base0 = ((size_t)b * Ss + r0) * Dd + h * DH;
        size_t base1 = base0 + 8 * Dd;
        #pragma unroll
        for (int nt = 0; nt < 8; nt++) {
            int cc = nt * 8 + 2 * cL;
            float x0 = o[mt][nt][0] * inv0, x1 = o[mt][nt][1] * inv0;
            float x2 = o[mt][nt][2] * inv1, x3 = o[mt][nt][3] * inv1;
            __nv_bfloat16 h0, l0, h1, l1, h2, l2, h3, l3;
            decb(x0, h0, l0); decb(x1, h1, l1);
            decb(x2, h2, l2); decb(x3, h3, l3);
            *(__nv_bfloat162*)(g_Oh + base0 + cc) = __nv_bfloat162(h0, h1);
            *(__nv_bfloat162*)(g_Ol + base0 + cc) = __nv_bfloat162(l0, l1);
            *(__nv_bfloat162*)(g_Oh + base1 + cc) = __nv_bfloat162(h2, h3);
            *(__nv_bfloat162*)(g_Ol + base1 + cc) = __nv_bfloat162(l2, l3);
        }
    }
}

// ---------------------------------------------------------------------------

extern "C" void kernel_launch(void* const* d_in, const int* in_sizes, int n_in,
                              void* d_out, int out_size)
{
    const float* x  = (const float*)d_in[0];
    const float* Wq = (const float*)d_in[1];
    const float* Wk = (const float*)d_in[2];
    const float* Wv = (const float*)d_in[3];
    const float* Wo = (const float*)d_in[4];
    float* out = (float*)d_out;

    const int GEMM_SMEM = 2 * GSTG_B;
    const int ATTN_SMEM = (PS_OFF + 128 * 72) * (int)sizeof(float);

    cudaFuncSetAttribute(gemm_qkv_tc, cudaFuncAttributeMaxDynamicSharedMemorySize, GEMM_SMEM);
    cudaFuncSetAttribute(gemm_out_tc, cudaFuncAttributeMaxDynamicSharedMemorySize, GEMM_SMEM);
    cudaFuncSetAttribute(attn_mma,    cudaFuncAttributeMaxDynamicSharedMemorySize, ATTN_SMEM);

    conv_all<<<512, 256>>>(x, Wq, Wk, Wv, Wo);
    gemm_qkv_tc<<<dim3(Mm / 128, Dd / 128, 3), 256, GEMM_SMEM>>>();
    attn_mma<<<dim3(Ss / 128, Hh, Bb), 128, ATTN_SMEM>>>();
    gemm_out_tc<<<dim3(Mm / 128, Dd / 128), 256, GEMM_SMEM>>>(out);
}

// round 9
// speedup vs baseline: 1.0008x; 1.0008x over previous
#include <cuda_runtime.h>
#include <cuda_bf16.h>
#include <float.h>
#include <stdint.h>

#define Bb 2
#define Ss 2048
#define Dd 768
#define Hh 12
#define DH 64
#define Mm (Bb*Ss)

// ---------------- scratch ----------------
__device__ float g_Q[(size_t)Bb*Hh*Ss*DH];
__device__ float g_K[(size_t)Bb*Hh*Ss*DH];
__device__ float g_V[(size_t)Bb*Hh*Ss*DH];
__device__ __nv_bfloat16 g_Oh[(size_t)Mm*Dd];
__device__ __nv_bfloat16 g_Ol[(size_t)Mm*Dd];
__device__ __nv_bfloat16 g_Xh[(size_t)Mm*Dd];
__device__ __nv_bfloat16 g_Xl[(size_t)Mm*Dd];
__device__ __nv_bfloat16 g_Wh[4][(size_t)Dd*Dd];
__device__ __nv_bfloat16 g_Wl[4][(size_t)Dd*Dd];

// ---------------- helpers ----------------
__device__ __forceinline__ uint32_t smem_u32(const void* p) {
    uint32_t a;
    asm("{ .reg .u64 t; cvta.to.shared.u64 t, %1; cvt.u32.u64 %0, t; }" : "=r"(a) : "l"(p));
    return a;
}
__device__ __forceinline__ void cp16(uint32_t dst, const void* src) {
    asm volatile("cp.async.cg.shared.global [%0], [%1], 16;"
        :: "r"(dst), "l"(__cvta_generic_to_global(src)));
}
__device__ __forceinline__ void cp_commit() { asm volatile("cp.async.commit_group;"); }
__device__ __forceinline__ void cp_wait0()  { asm volatile("cp.async.wait_group 0;"); }
__device__ __forceinline__ void cp_wait1()  { asm volatile("cp.async.wait_group 1;"); }

__device__ __forceinline__ float to_tf32(float x) {
    uint32_t u;
    asm("cvt.rna.tf32.f32 %0, %1;" : "=r"(u) : "f"(x));
    return __uint_as_float(u);
}
__device__ __forceinline__ uint32_t f2u(float x) { return __float_as_uint(x); }

// tf32 k8 MMA (attention)
__device__ __forceinline__ void mma8(float* d, const uint32_t* a, const uint32_t* b) {
    asm volatile("mma.sync.aligned.m16n8k8.row.col.f32.tf32.tf32.f32 "
        "{%0,%1,%2,%3}, {%4,%5,%6,%7}, {%8,%9}, {%0,%1,%2,%3};"
        : "+f"(d[0]), "+f"(d[1]), "+f"(d[2]), "+f"(d[3])
        : "r"(a[0]), "r"(a[1]), "r"(a[2]), "r"(a[3]), "r"(b[0]), "r"(b[1]));
}
// bf16 k16 MMA (dense GEMMs)
__device__ __forceinline__ void mma16(float* d, const uint32_t* a, const uint32_t* b) {
    asm volatile("mma.sync.aligned.m16n8k16.row.col.f32.bf16.bf16.f32 "
        "{%0,%1,%2,%3}, {%4,%5,%6,%7}, {%8,%9}, {%0,%1,%2,%3};"
        : "+f"(d[0]), "+f"(d[1]), "+f"(d[2]), "+f"(d[3])
        : "r"(a[0]), "r"(a[1]), "r"(a[2]), "r"(a[3]), "r"(b[0]), "r"(b[1]));
}
__device__ __forceinline__ void ldm4(uint32_t* r, uint32_t addr) {
    asm volatile("ldmatrix.sync.aligned.m8n8.x4.shared.b16 {%0,%1,%2,%3}, [%4];"
        : "=r"(r[0]), "=r"(r[1]), "=r"(r[2]), "=r"(r[3]) : "r"(addr));
}
__device__ __forceinline__ void decb(float x, __nv_bfloat16& h, __nv_bfloat16& l) {
    h = __float2bfloat16_rn(x);
    l = __float2bfloat16_rn(x - __bfloat162float(h));
}

// ---------------- pre-pass: fp32 -> bf16 hi/lo ----------------
__global__ void conv_all(const float* __restrict__ x,
                         const float* __restrict__ wq, const float* __restrict__ wk,
                         const float* __restrict__ wv, const float* __restrict__ wo) {
    int i = blockIdx.x * blockDim.x + threadIdx.x;
    int stride = gridDim.x * blockDim.x;
    for (int t = i; t < Mm * Dd; t += stride) decb(x[t], g_Xh[t], g_Xl[t]);
    const float* ws[4] = {wq, wk, wv, wo};
    for (int w = 0; w < 4; w++)
        for (int t = i; t < Dd * Dd; t += stride) decb(ws[w][t], g_Wh[w][t], g_Wl[w][t]);
}

// ---------------- bf16x3 GEMM core: CTA 128x96, BK=32, 3-stage ring ----------------
// 256 threads (8 warps: wm 0..3 -> 32 rows, wn 0..1 -> 48 cols), warp tile 32x48.
// Stage (bytes): Ah[128][80]=10240 | Al=10240 | Bh[96][80]=7680 | Bl=7680 -> 35840.
// 3 stages = 107520 B. Row stride 80 B: ldmatrix bank walk conflict-free.
#define GSTG_B 35840
#define OFF_AL 10240
#define OFF_BH 20480
#define OFF_BL 28160
#define GCH32 24            // 768 / 32

__device__ __forceinline__ void gemm_core_bf3(const __nv_bfloat16* __restrict__ Ah,
                                              const __nv_bfloat16* __restrict__ Al,
                                              const __nv_bfloat16* __restrict__ Bh,
                                              const __nv_bfloat16* __restrict__ Bl,
                                              char* smc, float acc[2][6][4]) {
    const int tid = threadIdx.x;
    const int lane = tid & 31;
    const int wid = tid >> 5;
    const int wm = wid >> 1, wn = wid & 1;

    uint32_t sb = smem_u32(smc);

    #pragma unroll
    for (int mt = 0; mt < 2; mt++)
        #pragma unroll
        for (int nt = 0; nt < 6; nt++)
            #pragma unroll
            for (int q = 0; q < 4; q++) acc[mt][nt][q] = 0.f;

    // A: 128 rows x 4 segs(16B) = 512 segs -> 2 per thread
    const int ra0 = tid >> 2, sa = tid & 3;
    const int ra1 = (256 + tid) >> 2;
    const uint32_t soA0 = (uint32_t)(ra0 * 80 + sa * 16);
    const uint32_t soA1 = (uint32_t)(ra1 * 80 + sa * 16);
    const size_t goA0 = (size_t)ra0 * Dd + sa * 8;
    const size_t goA1 = (size_t)ra1 * Dd + sa * 8;
    // B: 96 rows x 4 segs = 384 segs -> thread tid takes seg tid, and (tid<128) seg 256+tid
    const int rb0 = tid >> 2;                       // 0..63
    const int rb1 = (256 + tid) >> 2;               // 64..95 for tid<128
    const uint32_t soB0 = (uint32_t)(rb0 * 80 + sa * 16);
    const uint32_t soB1 = (uint32_t)(rb1 * 80 + sa * 16);
    const size_t goB0 = (size_t)rb0 * Dd + sa * 8;
    const size_t goB1 = (size_t)rb1 * Dd + sa * 8;
    const bool bTail = (tid < 128);

    // ldmatrix offsets
    const int arow = lane & 15, acolb = ((lane >> 4) << 4);
    const uint32_t aoff0 = (uint32_t)((wm * 32 + arow) * 80) + acolb;
    const uint32_t aoff1 = aoff0 + 16 * 80;
    const int brow = ((lane >> 4) << 3) + (lane & 7);
    const int bcolb = (((lane >> 3) & 1) << 4);
    uint32_t boff[3];
    #pragma unroll
    for (int p = 0; p < 3; p++)
        boff[p] = (uint32_t)((wn * 48 + p * 16 + brow) * 80) + bcolb;

    // chunk loader
    auto load_chunk = [&](int c, int stage) {
        uint32_t st = sb + stage * GSTG_B;
        const size_t kq = (size_t)c * 32;
        cp16(st + soA0,          Ah + goA0 + kq);
        cp16(st + soA1,          Ah + goA1 + kq);
        cp16(st + OFF_AL + soA0, Al + goA0 + kq);
        cp16(st + OFF_AL + soA1, Al + goA1 + kq);
        cp16(st + OFF_BH + soB0, Bh + goB0 + kq);
        cp16(st + OFF_BL + soB0, Bl + goB0 + kq);
        if (bTail) {
            cp16(st + OFF_BH + soB1, Bh + goB1 + kq);
            cp16(st + OFF_BL + soB1, Bl + goB1 + kq);
        }
        cp_commit();
    };

    // prologue: chunks 0,1 -> stages 0,1
    load_chunk(0, 0);
    load_chunk(1, 1);

    for (int c = 0; c < GCH32; c++) {
        if (c + 1 < GCH32) cp_wait1(); else cp_wait0();   // chunk c resident
        __syncthreads();                                   // stage (c+2)%3 free for rewrite
        if (c + 2 < GCH32) load_chunk(c + 2, (c + 2) % 3);

        const uint32_t st = sb + (c % 3) * GSTG_B;
        #pragma unroll
        for (int kh = 0; kh < 2; kh++) {
            const uint32_t ko = kh * 32;
            const uint32_t stA  = st + ko,           stAl = st + OFF_AL + ko;
            const uint32_t stB  = st + OFF_BH + ko,  stBl = st + OFF_BL + ko;

            uint32_t ah[2][4], al[2][4];
            ldm4(ah[0], stA  + aoff0);
            ldm4(ah[1], stA  + aoff1);
            ldm4(al[0], stAl + aoff0);
            ldm4(al[1], stAl + aoff1);

            uint32_t bh[2][4], bl[2][4];
            ldm4(bh[0], stB  + boff[0]);
            ldm4(bl[0], stBl + boff[0]);
            #pragma unroll
            for (int p = 0; p < 3; p++) {
                const int cur = p & 1, nxt = cur ^ 1;
                if (p < 2) {
                    ldm4(bh[nxt], stB  + boff[p + 1]);
                    ldm4(bl[nxt], stBl + boff[p + 1]);
                }
                #pragma unroll
                for (int j = 0; j < 2; j++)
                    #pragma unroll
                    for (int mt = 0; mt < 2; mt++)
                        mma16(acc[mt][p * 2 + j], al[mt], &bh[cur][2 * j]);
                #pragma unroll
                for (int j = 0; j < 2; j++)
                    #pragma unroll
                    for (int mt = 0; mt < 2; mt++)
                        mma16(acc[mt][p * 2 + j], ah[mt], &bl[cur][2 * j]);
                #pragma unroll
                for (int j = 0; j < 2; j++)
                    #pragma unroll
                    for (int mt = 0; mt < 2; mt++)
                        mma16(acc[mt][p * 2 + j], ah[mt], &bh[cur][2 * j]);
            }
        }
    }
}

// QKV projection: scatter fp32 (tf32-rounded, Q pre-scaled) into [B,H,S,DH]
__global__ __launch_bounds__(256, 2) void gemm_qkv_tc() {
    extern __shared__ char smc[];
    const int z = blockIdx.z;
    float* Obuf = (z == 0) ? g_Q : (z == 1 ? g_K : g_V);
    const float scale = (z == 0) ? 0.125f : 1.0f;
    const int mBase = blockIdx.x * 128, nBase = blockIdx.y * 96;

    float acc[2][6][4];
    gemm_core_bf3(g_Xh + (size_t)mBase * Dd, g_Xl + (size_t)mBase * Dd,
                  g_Wh[z] + (size_t)nBase * Dd, g_Wl[z] + (size_t)nBase * Dd,
                  smc, acc);

    const int lane = threadIdx.x & 31, wid = threadIdx.x >> 5;
    const int wm = wid >> 1, wn = wid & 1;
    #pragma unroll
    for (int mt = 0; mt < 2; mt++) {
        int r0 = mBase + wm * 32 + mt * 16 + (lane >> 2);
        #pragma unroll
        for (int half = 0; half < 2; half++) {
            int row = r0 + half * 8;
            int bb = row >> 11, ssi = row & 2047;
            #pragma unroll
            for (int nt = 0; nt < 6; nt++) {
                int colg = nBase + wn * 48 + nt * 8 + 2 * (lane & 3);
                int h = colg >> 6, dh = colg & 63;
                float* dst = Obuf + (((size_t)bb * Hh + h) * Ss + ssi) * DH + dh;
                *(float2*)dst = make_float2(
                    to_tf32(acc[mt][nt][half * 2 + 0] * scale),
                    to_tf32(acc[mt][nt][half * 2 + 1] * scale));
            }
        }
    }
}

// output projection: fp32 store to d_out
__global__ __launch_bounds__(256, 2) void gemm_out_tc(float* __restrict__ C) {
    extern __shared__ char smc[];
    const int mBase = blockIdx.x * 128, nBase = blockIdx.y * 96;

    float acc[2][6][4];
    gemm_core_bf3(g_Oh + (size_t)mBase * Dd, g_Ol + (size_t)mBase * Dd,
                  g_Wh[3] + (size_t)nBase * Dd, g_Wl[3] + (size_t)nBase * Dd,
                  smc, acc);

    const int lane = threadIdx.x & 31, wid = threadIdx.x >> 5;
    const int wm = wid >> 1, wn = wid & 1;
    #pragma unroll
    for (int mt = 0; mt < 2; mt++) {
        int r0 = mBase + wm * 32 + mt * 16 + (lane >> 2);
        #pragma unroll
        for (int half = 0; half < 2; half++) {
            int row = r0 + half * 8;
            float* dst = C + (size_t)row * Dd + nBase + wn * 48;
            #pragma unroll
            for (int nt = 0; nt < 6; nt++) {
                int d = nt * 8 + 2 * (lane & 3);
                *(float2*)(dst + d) = make_float2(acc[mt][nt][half * 2 + 0],
                                                  acc[mt][nt][half * 2 + 1]);
            }
        }
    }
}

// ---------------- flash attention (unchanged) ----------------
#define QS_OFF 0
#define KS_OFF 8704
#define VS_OFF 13056
#define PS_OFF 17664

__global__ __launch_bounds__(128) void attn_mma() {
    extern __shared__ float sm[];
    float* Qs = sm + QS_OFF;
    float* Ks = sm + KS_OFF;
    float* Vs = sm + VS_OFF;
    float* Ps = sm + PS_OFF;

    const int tid = threadIdx.x;
    const int lane = tid & 31, wid = tid >> 5;
    const int qt = gridDim.x - 1 - blockIdx.x;
    const int h = blockIdx.y, b = blockIdx.z;

    const float* Qg = g_Q + (((size_t)b * Hh + h) * Ss + (size_t)qt * 128) * DH;
    const float* Kg = g_K + (((size_t)b * Hh + h) * Ss) * DH;
    const float* Vg = g_V + (((size_t)b * Hh + h) * Ss) * DH;

    uint32_t sQ = smem_u32(Qs), sK = smem_u32(Ks), sV = smem_u32(Vs);

    #pragma unroll
    for (int t = 0; t < 16; t++) {
        int idx = tid + t * 128;
        int r = idx >> 4, c = (idx & 15) * 4;
        cp16(sQ + (r * 68 + c) * 4, Qg + r * DH + c);
    }
    cp_commit();

    float o[2][8][4];
    float mrow[2][2], lrow[2][2];
    #pragma unroll
    for (int mt = 0; mt < 2; mt++) {
        mrow[mt][0] = mrow[mt][1] = -1e30f;
        lrow[mt][0] = lrow[mt][1] = 0.f;
        #pragma unroll
        for (int nt = 0; nt < 8; nt++)
            #pragma unroll
            for (int q = 0; q < 4; q++) o[mt][nt][q] = 0.f;
    }

    const int cL = lane & 3, rL = lane >> 2;
    const int ktMax = 2 * qt + 1;

    for (int kt = 0; kt <= ktMax; kt++) {
        __syncthreads();
        const float* Kp = Kg + (size_t)kt * 64 * DH;
        const float* Vp = Vg + (size_t)kt * 64 * DH;
        #pragma unroll
        for (int t = 0; t < 8; t++) {
            int idx = tid + t * 128;
            int r = idx >> 4, c = (idx & 15) * 4;
            cp16(sK + (r * 68 + c) * 4, Kp + r * DH + c);
            cp16(sV + (r * 72 + c) * 4, Vp + r * DH + c);
        }
        cp_commit();
        cp_wait0();
        __syncthreads();

        float s[2][8][4];
        #pragma unroll
        for (int mt = 0; mt < 2; mt++)
            #pragma unroll
            for (int nt = 0; nt < 8; nt++)
                #pragma unroll
                for (int q = 0; q < 4; q++) s[mt][nt][q] = 0.f;

        #pragma unroll
        for (int ks = 0; ks < 8; ks++) {
            const int kb = ks * 8 + cL;
            uint32_t bfr[8][2];
            #pragma unroll
            for (int nt = 0; nt < 8; nt++) {
                const float* kp = Ks + (nt * 8 + rL) * 68;
                bfr[nt][0] = f2u(kp[kb]);
                bfr[nt][1] = f2u(kp[kb + 4]);
            }
            #pragma unroll
            for (int mt = 0; mt < 2; mt++) {
                const float* qp = Qs + (wid * 32 + mt * 16 + rL) * 68;
                uint32_t a[4];
                a[0] = f2u(qp[kb]);
                a[1] = f2u(qp[8 * 68 + kb]);
                a[2] = f2u(qp[kb + 4]);
                a[3] = f2u(qp[8 * 68 + kb + 4]);
                #pragma unroll
                for (int nt = 0; nt < 8; nt++) mma8(s[mt][nt], a, bfr[nt]);
            }
        }

        if (kt >= 2 * qt) {
            #pragma unroll
            for (int mt = 0; mt < 2; mt++) {
                int rg0 = qt * 128 + wid * 32 + mt * 16 + rL;
                #pragma unroll
                for (int nt = 0; nt < 8; nt++) {
                    int cg = kt * 64 + nt * 8 + 2 * cL;
                    if (cg     > rg0)     s[mt][nt][0] = -1e30f;
                    if (cg + 1 > rg0)     s[mt][nt][1] = -1e30f;
                    if (cg     > rg0 + 8) s[mt][nt][2] = -1e30f;
                    if (cg + 1 > rg0 + 8) s[mt][nt][3] = -1e30f;
                }
            }
        }

        #pragma unroll
        for (int mt = 0; mt < 2; mt++) {
            float v0 = -1e30f, v1 = -1e30f;
            #pragma unroll
            for (int nt = 0; nt < 8; nt++) {
                v0 = fmaxf(v0, fmaxf(s[mt][nt][0], s[mt][nt][1]));
                v1 = fmaxf(v1, fmaxf(s[mt][nt][2], s[mt][nt][3]));
            }
            v0 = fmaxf(v0, __shfl_xor_sync(0xffffffffu, v0, 1));
            v0 = fmaxf(v0, __shfl_xor_sync(0xffffffffu, v0, 2));
            v1 = fmaxf(v1, __shfl_xor_sync(0xffffffffu, v1, 1));
            v1 = fmaxf(v1, __shfl_xor_sync(0xffffffffu, v1, 2));

            float mn0 = fmaxf(mrow[mt][0], v0);
            float mn1 = fmaxf(mrow[mt][1], v1);
            float cr0 = __expf(mrow[mt][0] - mn0);
            float cr1 = __expf(mrow[mt][1] - mn1);
            mrow[mt][0] = mn0; mrow[mt][1] = mn1;

            float rs0 = 0.f, rs1 = 0.f;
            float* prow0 = Ps + (wid * 32 + mt * 16 + rL) * 72;
            float* prow1 = prow0 + 8 * 72;
            #pragma unroll
            for (int nt = 0; nt < 8; nt++) {
                float p0 = __expf(s[mt][nt][0] - mn0);
                float p1 = __expf(s[mt][nt][1] - mn0);
                float p2 = __expf(s[mt][nt][2] - mn1);
                float p3 = __expf(s[mt][nt][3] - mn1);
                rs0 += p0 + p1; rs1 += p2 + p3;
                int cc = nt * 8 + 2 * cL;
                *(float2*)(prow0 + cc) = make_float2(to_tf32(p0), to_tf32(p1));
                *(float2*)(prow1 + cc) = make_float2(to_tf32(p2), to_tf32(p3));
            }
            rs0 += __shfl_xor_sync(0xffffffffu, rs0, 1);
            rs0 += __shfl_xor_sync(0xffffffffu, rs0, 2);
            rs1 += __shfl_xor_sync(0xffffffffu, rs1, 1);
            rs1 += __shfl_xor_sync(0xffffffffu, rs1, 2);
            lrow[mt][0] = lrow[mt][0] * cr0 + rs0;
            lrow[mt][1] = lrow[mt][1] * cr1 + rs1;
            #pragma unroll
            for (int nt = 0; nt < 8; nt++) {
                o[mt][nt][0] *= cr0; o[mt][nt][1] *= cr0;
                o[mt][nt][2] *= cr1; o[mt][nt][3] *= cr1;
            }
        }
        __syncwarp();

        #pragma unroll
        for (int ks = 0; ks < 8; ks++) {
            const int kb = ks * 8;
            uint32_t bfr[8][2];
            #pragma unroll
            for (int nt = 0; nt < 8; nt++) {
                bfr[nt][0] = f2u(Vs[(kb + cL) * 72 + nt * 8 + rL]);
                bfr[nt][1] = f2u(Vs[(kb + 4 + cL) * 72 + nt * 8 + rL]);
            }
            #pragma unroll
            for (int mt = 0; mt < 2; mt++) {
                const float* pp = Ps + (wid * 32 + mt * 16 + rL) * 72;
                uint32_t a[4];
                a[0] = f2u(pp[kb + cL]);
                a[1] = f2u(pp[8 * 72 + kb + cL]);
                a[2] = f2u(pp[kb + 4 + cL]);
                a[3] = f2u(pp[8 * 72 + kb + 4 + cL]);
                #pragma unroll
                for (int nt = 0; nt < 8; nt++) mma8(o[mt][nt], a, bfr[nt]);
            }
        }
    }

    #pragma unroll
    for (int mt = 0; mt < 2; mt++) {
        float inv0 = 1.f / lrow[mt][0];
        float inv1 = 1.f / lrow[mt][1];
        int r0 = qt * 128 + wid * 32 + mt * 16 + rL;
        size_t base0 = ((size_t)b * Ss + r0) * Dd + h * DH;
        size_t base1 = base0 + 8 * Dd;
        #pragma unroll
        for (int nt = 0; nt < 8; nt++) {
            int cc = nt * 8 + 2 * cL;
            float x0 = o[mt][nt][0] * inv0, x1 = o[mt][nt][1] * inv0;
            float x2 = o[mt][nt][2] * inv1, x3 = o[mt][nt][3] * inv1;
            __nv_bfloat16 h0, l0, h1, l1, h2, l2, h3, l3;
            decb(x0, h0, l0); decb(x1, h1, l1);
            decb(x2, h2, l2); decb(x3, h3, l3);
            *(__nv_bfloat162*)(g_Oh + base0 + cc) = __nv_bfloat162(h0, h1);
            *(__nv_bfloat162*)(g_Ol + base0 + cc) = __nv_bfloat162(l0, l1);
            *(__nv_bfloat162*)(g_Oh + base1 + cc) = __nv_bfloat162(h2, h3);
            *(__nv_bfloat162*)(g_Ol + base1 + cc) = __nv_bfloat162(l2, l3);
        }
    }
}

// ---------------------------------------------------------------------------

extern "C" void kernel_launch(void* const* d_in, const int* in_sizes, int n_in,
                              void* d_out, int out_size)
{
    const float* x  = (const float*)d_in[0];
    const float* Wq = (const float*)d_in[1];
    const float* Wk = (const float*)d_in[2];
    const float* Wv = (const float*)d_in[3];
    const float* Wo = (const float*)d_in[4];
    float* out = (float*)d_out;

    const int GEMM_SMEM = 3 * GSTG_B;                          // 107520
    const int ATTN_SMEM = (PS_OFF + 128 * 72) * (int)sizeof(float);

    cudaFuncSetAttribute(gemm_qkv_tc, cudaFuncAttributeMaxDynamicSharedMemorySize, GEMM_SMEM);
    cudaFuncSetAttribute(gemm_out_tc, cudaFuncAttributeMaxDynamicSharedMemorySize, GEMM_SMEM);
    cudaFuncSetAttribute(attn_mma,    cudaFuncAttributeMaxDynamicSharedMemorySize, ATTN_SMEM);

    conv_all<<<512, 256>>>(x, Wq, Wk, Wv, Wo);
    gemm_qkv_tc<<<dim3(Mm / 128, Dd / 96, 3), 256, GEMM_SMEM>>>();
    attn_mma<<<dim3(Ss / 128, Hh, Bb), 128, ATTN_SMEM>>>();
    gemm_out_tc<<<dim3(Mm / 128, Dd / 96), 256, GEMM_SMEM>>>(out);
}

// round 10
// speedup vs baseline: 1.0017x; 1.0010x over previous
#include <cuda_runtime.h>
#include <cuda_bf16.h>
#include <float.h>
#include <stdint.h>

#define Bb 2
#define Ss 2048
#define Dd 768
#define Hh 12
#define DH 64
#define Mm (Bb*Ss)

// ---------------- scratch ----------------
__device__ float g_Q[(size_t)Bb*Hh*Ss*DH];
__device__ float g_K[(size_t)Bb*Hh*Ss*DH];
__device__ float g_V[(size_t)Bb*Hh*Ss*DH];
__device__ __nv_bfloat16 g_Oh[(size_t)Mm*Dd];
__device__ __nv_bfloat16 g_Ol[(size_t)Mm*Dd];
__device__ __nv_bfloat16 g_Xh[(size_t)Mm*Dd];
__device__ __nv_bfloat16 g_Xl[(size_t)Mm*Dd];
__device__ __nv_bfloat16 g_Wh[4][(size_t)Dd*Dd];
__device__ __nv_bfloat16 g_Wl[4][(size_t)Dd*Dd];

// ---------------- helpers ----------------
__device__ __forceinline__ uint32_t smem_u32(const void* p) {
    uint32_t a;
    asm("{ .reg .u64 t; cvta.to.shared.u64 t, %1; cvt.u32.u64 %0, t; }" : "=r"(a) : "l"(p));
    return a;
}
__device__ __forceinline__ void cp16(uint32_t dst, const void* src) {
    asm volatile("cp.async.cg.shared.global [%0], [%1], 16;"
        :: "r"(dst), "l"(__cvta_generic_to_global(src)));
}
__device__ __forceinline__ void cp_commit() { asm volatile("cp.async.commit_group;"); }
__device__ __forceinline__ void cp_wait0()  { asm volatile("cp.async.wait_group 0;"); }

__device__ __forceinline__ float to_tf32(float x) {
    uint32_t u;
    asm("cvt.rna.tf32.f32 %0, %1;" : "=r"(u) : "f"(x));
    return __uint_as_float(u);
}
__device__ __forceinline__ uint32_t f2u(float x) { return __float_as_uint(x); }

// tf32 k8 MMA (attention)
__device__ __forceinline__ void mma8(float* d, const uint32_t* a, const uint32_t* b) {
    asm volatile("mma.sync.aligned.m16n8k8.row.col.f32.tf32.tf32.f32 "
        "{%0,%1,%2,%3}, {%4,%5,%6,%7}, {%8,%9}, {%0,%1,%2,%3};"
        : "+f"(d[0]), "+f"(d[1]), "+f"(d[2]), "+f"(d[3])
        : "r"(a[0]), "r"(a[1]), "r"(a[2]), "r"(a[3]), "r"(b[0]), "r"(b[1]));
}
// bf16 k16 MMA (dense GEMMs)
__device__ __forceinline__ void mma16(float* d, const uint32_t* a, const uint32_t* b) {
    asm volatile("mma.sync.aligned.m16n8k16.row.col.f32.bf16.bf16.f32 "
        "{%0,%1,%2,%3}, {%4,%5,%6,%7}, {%8,%9}, {%0,%1,%2,%3};"
        : "+f"(d[0]), "+f"(d[1]), "+f"(d[2]), "+f"(d[3])
        : "r"(a[0]), "r"(a[1]), "r"(a[2]), "r"(a[3]), "r"(b[0]), "r"(b[1]));
}
__device__ __forceinline__ void ldm4(uint32_t* r, uint32_t addr) {
    asm volatile("ldmatrix.sync.aligned.m8n8.x4.shared.b16 {%0,%1,%2,%3}, [%4];"
        : "=r"(r[0]), "=r"(r[1]), "=r"(r[2]), "=r"(r[3]) : "r"(addr));
}
__device__ __forceinline__ void decb(float x, __nv_bfloat16& h, __nv_bfloat16& l) {
    h = __float2bfloat16_rn(x);
    l = __float2bfloat16_rn(x - __bfloat162float(h));
}

// ---------------- pre-pass: fp32 -> bf16 hi/lo ----------------
__global__ void conv_all(const float* __restrict__ x,
                         const float* __restrict__ wq, const float* __restrict__ wk,
                         const float* __restrict__ wv, const float* __restrict__ wo) {
    int i = blockIdx.x * blockDim.x + threadIdx.x;
    int stride = gridDim.x * blockDim.x;
    for (int t = i; t < Mm * Dd; t += stride) decb(x[t], g_Xh[t], g_Xl[t]);
    const float* ws[4] = {wq, wk, wv, wo};
    for (int w = 0; w < 4; w++)
        for (int t = i; t < Dd * Dd; t += stride) decb(ws[w][t], g_Wh[w][t], g_Wl[w][t]);
}

// ---------------- bf16x3 GEMM core: CTA 128x64, BK=32, 2-stage, 3 CTAs/SM ----------------
// 256 threads (8 warps: wm 0..3 -> 32 rows, wn 0..1 -> 32 cols), warp tile 32x32.
// Stage (bytes): Ah[128][80]=10240 | Al=10240 | Bh[64][80]=5120 | Bl=5120 -> 30720.
// 2 stages = 61440 B -> 3 CTAs/SM (<=85 regs enforced via launch_bounds).
#define GSTG_B 30720
#define OFF_AL 10240
#define OFF_BH 20480
#define OFF_BL 25600
#define GCH32 24            // 768 / 32

__device__ __forceinline__ void gemm_core_bf3(const __nv_bfloat16* __restrict__ Ah,
                                              const __nv_bfloat16* __restrict__ Al,
                                              const __nv_bfloat16* __restrict__ Bh,
                                              const __nv_bfloat16* __restrict__ Bl,
                                              char* smc, float acc[2][4][4]) {
    const int tid = threadIdx.x;
    const int lane = tid & 31;
    const int wid = tid >> 5;
    const int wm = wid >> 1, wn = wid & 1;

    uint32_t sb = smem_u32(smc);

    #pragma unroll
    for (int mt = 0; mt < 2; mt++)
        #pragma unroll
        for (int nt = 0; nt < 4; nt++)
            #pragma unroll
            for (int q = 0; q < 4; q++) acc[mt][nt][q] = 0.f;

    // A: 128 rows x 4 segs(16B) = 512 segs -> 2 per thread
    const int ra0 = tid >> 2, sa = tid & 3;
    const int ra1 = (256 + tid) >> 2;
    const uint32_t soA0 = (uint32_t)(ra0 * 80 + sa * 16);
    const uint32_t soA1 = (uint32_t)(ra1 * 80 + sa * 16);
    const size_t goA0 = (size_t)ra0 * Dd + sa * 8;
    const size_t goA1 = (size_t)ra1 * Dd + sa * 8;
    // B: 64 rows x 4 segs = 256 segs -> 1 per thread
    const uint32_t soB0 = (uint32_t)(ra0 * 80 + sa * 16);   // ra0 in 0..63
    const size_t goB0 = (size_t)ra0 * Dd + sa * 8;

    // ldmatrix offsets
    const int arow = lane & 15, acolb = ((lane >> 4) << 4);
    const uint32_t aoff0 = (uint32_t)((wm * 32 + arow) * 80) + acolb;
    const uint32_t aoff1 = aoff0 + 16 * 80;
    const int brow = ((lane >> 4) << 3) + (lane & 7);
    const int bcolb = (((lane >> 3) & 1) << 4);
    uint32_t boff[2];
    #pragma unroll
    for (int p = 0; p < 2; p++)
        boff[p] = (uint32_t)((wn * 32 + p * 16 + brow) * 80) + bcolb;

    auto load_chunk = [&](int c, int stage) {
        uint32_t st = sb + stage * GSTG_B;
        const size_t kq = (size_t)c * 32;
        cp16(st + soA0,          Ah + goA0 + kq);
        cp16(st + soA1,          Ah + goA1 + kq);
        cp16(st + OFF_AL + soA0, Al + goA0 + kq);
        cp16(st + OFF_AL + soA1, Al + goA1 + kq);
        cp16(st + OFF_BH + soB0, Bh + goB0 + kq);
        cp16(st + OFF_BL + soB0, Bl + goB0 + kq);
        cp_commit();
    };

    load_chunk(0, 0);

    for (int c = 0; c < GCH32; c++) {
        cp_wait0();
        __syncthreads();
        if (c + 1 < GCH32) load_chunk(c + 1, (c + 1) & 1);

        const uint32_t st = sb + (c & 1) * GSTG_B;
        #pragma unroll
        for (int kh = 0; kh < 2; kh++) {
            const uint32_t ko = kh * 32;
            const uint32_t stA  = st + ko,           stAl = st + OFF_AL + ko;
            const uint32_t stB  = st + OFF_BH + ko,  stBl = st + OFF_BL + ko;

            uint32_t ah[2][4], al[2][4];
            ldm4(ah[0], stA  + aoff0);
            ldm4(ah[1], stA  + aoff1);
            ldm4(al[0], stAl + aoff0);
            ldm4(al[1], stAl + aoff1);

            uint32_t bh[2][4], bl[2][4];
            ldm4(bh[0], stB  + boff[0]);
            ldm4(bl[0], stBl + boff[0]);
            #pragma unroll
            for (int p = 0; p < 2; p++) {
                const int cur = p & 1, nxt = cur ^ 1;
                if (p < 1) {
                    ldm4(bh[nxt], stB  + boff[1]);
                    ldm4(bl[nxt], stBl + boff[1]);
                }
                #pragma unroll
                for (int j = 0; j < 2; j++)
                    #pragma unroll
                    for (int mt = 0; mt < 2; mt++)
                        mma16(acc[mt][p * 2 + j], al[mt], &bh[cur][2 * j]);
                #pragma unroll
                for (int j = 0; j < 2; j++)
                    #pragma unroll
                    for (int mt = 0; mt < 2; mt++)
                        mma16(acc[mt][p * 2 + j], ah[mt], &bl[cur][2 * j]);
                #pragma unroll
                for (int j = 0; j < 2; j++)
                    #pragma unroll
                    for (int mt = 0; mt < 2; mt++)
                        mma16(acc[mt][p * 2 + j], ah[mt], &bh[cur][2 * j]);
            }
        }
    }
}

// QKV projection: scatter fp32 (tf32-rounded, Q pre-scaled) into [B,H,S,DH]
__global__ __launch_bounds__(256, 3) void gemm_qkv_tc() {
    extern __shared__ char smc[];
    const int z = blockIdx.z;
    float* Obuf = (z == 0) ? g_Q : (z == 1 ? g_K : g_V);
    const float scale = (z == 0) ? 0.125f : 1.0f;
    const int mBase = blockIdx.x * 128, nBase = blockIdx.y * 64;

    float acc[2][4][4];
    gemm_core_bf3(g_Xh + (size_t)mBase * Dd, g_Xl + (size_t)mBase * Dd,
                  g_Wh[z] + (size_t)nBase * Dd, g_Wl[z] + (size_t)nBase * Dd,
                  smc, acc);

    const int lane = threadIdx.x & 31, wid = threadIdx.x >> 5;
    const int wm = wid >> 1, wn = wid & 1;
    #pragma unroll
    for (int mt = 0; mt < 2; mt++) {
        int r0 = mBase + wm * 32 + mt * 16 + (lane >> 2);
        #pragma unroll
        for (int half = 0; half < 2; half++) {
            int row = r0 + half * 8;
            int bb = row >> 11, ssi = row & 2047;
            #pragma unroll
            for (int nt = 0; nt < 4; nt++) {
                int colg = nBase + wn * 32 + nt * 8 + 2 * (lane & 3);
                int h = colg >> 6, dh = colg & 63;
                float* dst = Obuf + (((size_t)bb * Hh + h) * Ss + ssi) * DH + dh;
                *(float2*)dst = make_float2(
                    to_tf32(acc[mt][nt][half * 2 + 0] * scale),
                    to_tf32(acc[mt][nt][half * 2 + 1] * scale));
            }
        }
    }
}

// output projection: fp32 store to d_out
__global__ __launch_bounds__(256, 3) void gemm_out_tc(float* __restrict__ C) {
    extern __shared__ char smc[];
    const int mBase = blockIdx.x * 128, nBase = blockIdx.y * 64;

    float acc[2][4][4];
    gemm_core_bf3(g_Oh + (size_t)mBase * Dd, g_Ol + (size_t)mBase * Dd,
                  g_Wh[3] + (size_t)nBase * Dd, g_Wl[3] + (size_t)nBase * Dd,
                  smc, acc);

    const int lane = threadIdx.x & 31, wid = threadIdx.x >> 5;
    const int wm = wid >> 1, wn = wid & 1;
    #pragma unroll
    for (int mt = 0; mt < 2; mt++) {
        int r0 = mBase + wm * 32 + mt * 16 + (lane >> 2);
        #pragma unroll
        for (int half = 0; half < 2; half++) {
            int row = r0 + half * 8;
            float* dst = C + (size_t)row * Dd + nBase + wn * 32;
            #pragma unroll
            for (int nt = 0; nt < 4; nt++) {
                int d = nt * 8 + 2 * (lane & 3);
                *(float2*)(dst + d) = make_float2(acc[mt][nt][half * 2 + 0],
                                                  acc[mt][nt][half * 2 + 1]);
            }
        }
    }
}

// ---------------- flash attention (unchanged) ----------------
#define QS_OFF 0
#define KS_OFF 8704
#define VS_OFF 13056
#define PS_OFF 17664

__global__ __launch_bounds__(128) void attn_mma() {
    extern __shared__ float sm[];
    float* Qs = sm + QS_OFF;
    float* Ks = sm + KS_OFF;
    float* Vs = sm + VS_OFF;
    float* Ps = sm + PS_OFF;

    const int tid = threadIdx.x;
    const int lane = tid & 31, wid = tid >> 5;
    const int qt = gridDim.x - 1 - blockIdx.x;
    const int h = blockIdx.y, b = blockIdx.z;

    const float* Qg = g_Q + (((size_t)b * Hh + h) * Ss + (size_t)qt * 128) * DH;
    const float* Kg = g_K + (((size_t)b * Hh + h) * Ss) * DH;
    const float* Vg = g_V + (((size_t)b * Hh + h) * Ss) * DH;

    uint32_t sQ = smem_u32(Qs), sK = smem_u32(Ks), sV = smem_u32(Vs);

    #pragma unroll
    for (int t = 0; t < 16; t++) {
        int idx = tid + t * 128;
        int r = idx >> 4, c = (idx & 15) * 4;
        cp16(sQ + (r * 68 + c) * 4, Qg + r * DH + c);
    }
    cp_commit();

    float o[2][8][4];
    float mrow[2][2], lrow[2][2];
    #pragma unroll
    for (int mt = 0; mt < 2; mt++) {
        mrow[mt][0] = mrow[mt][1] = -1e30f;
        lrow[mt][0] = lrow[mt][1] = 0.f;
        #pragma unroll
        for (int nt = 0; nt < 8; nt++)
            #pragma unroll
            for (int q = 0; q < 4; q++) o[mt][nt][q] = 0.f;
    }

    const int cL = lane & 3, rL = lane >> 2;
    const int ktMax = 2 * qt + 1;

    for (int kt = 0; kt <= ktMax; kt++) {
        __syncthreads();
        const float* Kp = Kg + (size_t)kt * 64 * DH;
        const float* Vp = Vg + (size_t)kt * 64 * DH;
        #pragma unroll
        for (int t = 0; t < 8; t++) {
            int idx = tid + t * 128;
            int r = idx >> 4, c = (idx & 15) * 4;
            cp16(sK + (r * 68 + c) * 4, Kp + r * DH + c);
            cp16(sV + (r * 72 + c) * 4, Vp + r * DH + c);
        }
        cp_commit();
        cp_wait0();
        __syncthreads();

        float s[2][8][4];
        #pragma unroll
        for (int mt = 0; mt < 2; mt++)
            #pragma unroll
            for (int nt = 0; nt < 8; nt++)
                #pragma unroll
                for (int q = 0; q < 4; q++) s[mt][nt][q] = 0.f;

        #pragma unroll
        for (int ks = 0; ks < 8; ks++) {
            const int kb = ks * 8 + cL;
            uint32_t bfr[8][2];
            #pragma unroll
            for (int nt = 0; nt < 8; nt++) {
                const float* kp = Ks + (nt * 8 + rL) * 68;
                bfr[nt][0] = f2u(kp[kb]);
                bfr[nt][1] = f2u(kp[kb + 4]);
            }
            #pragma unroll
            for (int mt = 0; mt < 2; mt++) {
                const float* qp = Qs + (wid * 32 + mt * 16 + rL) * 68;
                uint32_t a[4];
                a[0] = f2u(qp[kb]);
                a[1] = f2u(qp[8 * 68 + kb]);
                a[2] = f2u(qp[kb + 4]);
                a[3] = f2u(qp[8 * 68 + kb + 4]);
                #pragma unroll
                for (int nt = 0; nt < 8; nt++) mma8(s[mt][nt], a, bfr[nt]);
            }
        }

        if (kt >= 2 * qt) {
            #pragma unroll
            for (int mt = 0; mt < 2; mt++) {
                int rg0 = qt * 128 + wid * 32 + mt * 16 + rL;
                #pragma unroll
                for (int nt = 0; nt < 8; nt++) {
                    int cg = kt * 64 + nt * 8 + 2 * cL;
                    if (cg     > rg0)     s[mt][nt][0] = -1e30f;
                    if (cg + 1 > rg0)     s[mt][nt][1] = -1e30f;
                    if (cg     > rg0 + 8) s[mt][nt][2] = -1e30f;
                    if (cg + 1 > rg0 + 8) s[mt][nt][3] = -1e30f;
                }
            }
        }

        #pragma unroll
        for (int mt = 0; mt < 2; mt++) {
            float v0 = -1e30f, v1 = -1e30f;
            #pragma unroll
            for (int nt = 0; nt < 8; nt++) {
                v0 = fmaxf(v0, fmaxf(s[mt][nt][0], s[mt][nt][1]));
                v1 = fmaxf(v1, fmaxf(s[mt][nt][2], s[mt][nt][3]));
            }
            v0 = fmaxf(v0, __shfl_xor_sync(0xffffffffu, v0, 1));
            v0 = fmaxf(v0, __shfl_xor_sync(0xffffffffu, v0, 2));
            v1 = fmaxf(v1, __shfl_xor_sync(0xffffffffu, v1, 1));
            v1 = fmaxf(v1, __shfl_xor_sync(0xffffffffu, v1, 2));

            float mn0 = fmaxf(mrow[mt][0], v0);
            float mn1 = fmaxf(mrow[mt][1], v1);
            float cr0 = __expf(mrow[mt][0] - mn0);
            float cr1 = __expf(mrow[mt][1] - mn1);
            mrow[mt][0] = mn0; mrow[mt][1] = mn1;

            float rs0 = 0.f, rs1 = 0.f;
            float* prow0 = Ps + (wid * 32 + mt * 16 + rL) * 72;
            float* prow1 = prow0 + 8 * 72;
            #pragma unroll
            for (int nt = 0; nt < 8; nt++) {
                float p0 = __expf(s[mt][nt][0] - mn0);
                float p1 = __expf(s[mt][nt][1] - mn0);
                float p2 = __expf(s[mt][nt][2] - mn1);
                float p3 = __expf(s[mt][nt][3] - mn1);
                rs0 += p0 + p1; rs1 += p2 + p3;
                int cc = nt * 8 + 2 * cL;
                *(float2*)(prow0 + cc) = make_float2(to_tf32(p0), to_tf32(p1));
                *(float2*)(prow1 + cc) = make_float2(to_tf32(p2), to_tf32(p3));
            }
            rs0 += __shfl_xor_sync(0xffffffffu, rs0, 1);
            rs0 += __shfl_xor_sync(0xffffffffu, rs0, 2);
            rs1 += __shfl_xor_sync(0xffffffffu, rs1, 1);
            rs1 += __shfl_xor_sync(0xffffffffu, rs1, 2);
            lrow[mt][0] = lrow[mt][0] * cr0 + rs0;
            lrow[mt][1] = lrow[mt][1] * cr1 + rs1;
            #pragma unroll
            for (int nt = 0; nt < 8; nt++) {
                o[mt][nt][0] *= cr0; o[mt][nt][1] *= cr0;
                o[mt][nt][2] *= cr1; o[mt][nt][3] *= cr1;
            }
        }
        __syncwarp();

        #pragma unroll
        for (int ks = 0; ks < 8; ks++) {
            const int kb = ks * 8;
            uint32_t bfr[8][2];
            #pragma unroll
            for (int nt = 0; nt < 8; nt++) {
                bfr[nt][0] = f2u(Vs[(kb + cL) * 72 + nt * 8 + rL]);
                bfr[nt][1] = f2u(Vs[(kb + 4 + cL) * 72 + nt * 8 + rL]);
            }
            #pragma unroll
            for (int mt = 0; mt < 2; mt++) {
                const float* pp = Ps + (wid * 32 + mt * 16 + rL) * 72;
                uint32_t a[4];
                a[0] = f2u(pp[kb + cL]);
                a[1] = f2u(pp[8 * 72 + kb + cL]);
                a[2] = f2u(pp[kb + 4 + cL]);
                a[3] = f2u(pp[8 * 72 + kb + 4 + cL]);
                #pragma unroll
                for (int nt = 0; nt < 8; nt++) mma8(o[mt][nt], a, bfr[nt]);
            }
        }
    }

    #pragma unroll
    for (int mt = 0; mt < 2; mt++) {
        float inv0 = 1.f / lrow[mt][0];
        float inv1 = 1.f / lrow[mt][1];
        int r0 = qt * 128 + wid * 32 + mt * 16 + rL;
        size_t base0 = ((size_t)b * Ss + r0) * Dd + h * DH;
        size_t base1 = base0 + 8 * Dd;
        #pragma unroll
        for (int nt = 0; nt < 8; nt++) {
            int cc = nt * 8 + 2 * cL;
            float x0 = o[mt][nt][0] * inv0, x1 = o[mt][nt][1] * inv0;
            float x2 = o[mt][nt][2] * inv1, x3 = o[mt][nt][3] * inv1;
            __nv_bfloat16 h0, l0, h1, l1, h2, l2, h3, l3;
            decb(x0, h0, l0); decb(x1, h1, l1);
            decb(x2, h2, l2); decb(x3, h3, l3);
            *(__nv_bfloat162*)(g_Oh + base0 + cc) = __nv_bfloat162(h0, h1);
            *(__nv_bfloat162*)(g_Ol + base0 + cc) = __nv_bfloat162(l0, l1);
            *(__nv_bfloat162*)(g_Oh + base1 + cc) = __nv_bfloat162(h2, h3);
            *(__nv_bfloat162*)(g_Ol + base1 + cc) = __nv_bfloat162(l2, l3);
        }
    }
}

// ---------------------------------------------------------------------------

extern "C" void kernel_launch(void* const* d_in, const int* in_sizes, int n_in,
                              void* d_out, int out_size)
{
    const float* x  = (const float*)d_in[0];
    const float* Wq = (const float*)d_in[1];
    const float* Wk = (const float*)d_in[2];
    const float* Wv = (const float*)d_in[3];
    const float* Wo = (const float*)d_in[4];
    float* out = (float*)d_out;

    const int GEMM_SMEM = 2 * GSTG_B;                          // 61440
    const int ATTN_SMEM = (PS_OFF + 128 * 72) * (int)sizeof(float);

    cudaFuncSetAttribute(gemm_qkv_tc, cudaFuncAttributeMaxDynamicSharedMemorySize, GEMM_SMEM);
    cudaFuncSetAttribute(gemm_out_tc, cudaFuncAttributeMaxDynamicSharedMemorySize, GEMM_SMEM);
    cudaFuncSetAttribute(attn_mma,    cudaFuncAttributeMaxDynamicSharedMemorySize, ATTN_SMEM);

    conv_all<<<512, 256>>>(x, Wq, Wk, Wv, Wo);
    gemm_qkv_tc<<<dim3(Mm / 128, Dd / 64, 3), 256, GEMM_SMEM>>>();
    attn_mma<<<dim3(Ss / 128, Hh, Bb), 128, ATTN_SMEM>>>();
    gemm_out_tc<<<dim3(Mm / 128, Dd / 64), 256, GEMM_SMEM>>>(out);
}